// round 1
// baseline (speedup 1.0000x reference)
#include <cuda_runtime.h>
#include <cstdint>
#include <math.h>

#define D_MODEL 2048
#define SEQ 16
#define BATCH 256
#define TOK (BATCH * SEQ)          // 4096
#define HALF_D (D_MODEL / 2)       // 1024

// ---------------- GEMM config ----------------
#define BM 128
#define BN 128
#define BK 32
#define STAGES 3
#define PITCH 36                   // floats per smem row (pad vs bank conflicts; 36*4=144 is 16B aligned)
#define STAGE_FLOATS ((BM + BN) * PITCH)
#define SMEM_BYTES (STAGES * STAGE_FLOATS * 4)
#define KTILES (D_MODEL / BK)      // 64

// ---------------- scratch (no cudaMalloc allowed) ----------------
__device__ float g_q[TOK * D_MODEL];
__device__ float g_k[TOK * D_MODEL];
__device__ float g_v[TOK * D_MODEL];
__device__ float g_cosT[SEQ * HALF_D];
__device__ float g_sinT[SEQ * HALF_D];

// ---------------- rotary tables (fp64, faithful to reference incl. the i-1 bug) ----------------
__global__ void rope_tables_kernel() {
    int idx = blockIdx.x * blockDim.x + threadIdx.x;
    if (idx >= SEQ * HALF_D) return;
    int m = idx / HALF_D;
    int i = idx - m * HALF_D;
    double theta = pow(10000.0, -2.0 * ((double)i - 1.0) / (double)D_MODEL);
    double ang = (double)m * theta;
    g_cosT[idx] = (float)cos(ang);
    g_sinT[idx] = (float)sin(ang);
}

// ---------------- helpers ----------------
__device__ __forceinline__ uint32_t f2tf32(float f) {
    uint32_t r;
    asm("cvt.rna.tf32.f32 %0, %1;" : "=r"(r) : "f"(f));
    return r;
}

__device__ __forceinline__ void mma_tf32(float* c, const uint32_t* a, const uint32_t* b) {
    asm volatile(
        "mma.sync.aligned.m16n8k8.row.col.f32.tf32.tf32.f32 "
        "{%0,%1,%2,%3}, {%4,%5,%6,%7}, {%8,%9}, {%0,%1,%2,%3};"
        : "+f"(c[0]), "+f"(c[1]), "+f"(c[2]), "+f"(c[3])
        : "r"(a[0]), "r"(a[1]), "r"(a[2]), "r"(a[3]),
          "r"(b[0]), "r"(b[1]));
}

__device__ __forceinline__ void cp16(uint32_t saddr, const float* gaddr) {
    asm volatile("cp.async.cg.shared.global [%0], [%1], 16;" :: "r"(saddr), "l"(gaddr));
}

// ---------------- fused QKV GEMM + rotary epilogue ----------------
// C[t][e] = sum_d X[t][d] * W[e][d]   (y = x @ W^T), then rotary for q/k.
// grid = (2048/BN, 4096/BM, 3), block = 256 threads (8 warps, 4x2 warp grid).
__global__ __launch_bounds__(256, 1)
void qkv_gemm_kernel(const float* __restrict__ x,
                     const float* __restrict__ wq,
                     const float* __restrict__ wk,
                     const float* __restrict__ wv) {
    extern __shared__ float smem[];
    const int tid   = threadIdx.x;
    const int lane  = tid & 31;
    const int warp  = tid >> 5;
    const int warpM = warp >> 1;        // 0..3 -> 32-row slabs
    const int warpN = warp & 1;         // 0..1 -> 64-col slabs
    const int lr    = lane >> 2;        // groupID
    const int lc    = lane & 3;         // tid in group
    const int mat   = blockIdx.z;
    const int mBase = blockIdx.y * BM;
    const int nBase = blockIdx.x * BN;

    const float* W   = (mat == 0) ? wq : (mat == 1) ? wk : wv;
    float*       out = (mat == 0) ? g_q : (mat == 1) ? g_k : g_v;

    const uint32_t s0 = (uint32_t)__cvta_generic_to_shared(smem);
    const int rA = tid >> 3;            // load row within 32-row pass
    const int c4 = (tid & 7) * 4;       // load col (float4)

    float acc[2][8][4];
#pragma unroll
    for (int mt = 0; mt < 2; ++mt)
#pragma unroll
        for (int nt = 0; nt < 8; ++nt)
#pragma unroll
            for (int i = 0; i < 4; ++i) acc[mt][nt][i] = 0.f;

    auto load_stage = [&](int kt, int s) {
        if (kt < KTILES) {
            const int kBase = kt * BK;
            const uint32_t sa = s0 + (uint32_t)(s * STAGE_FLOATS) * 4u;
            const uint32_t sb = sa + (uint32_t)(BM * PITCH) * 4u;
#pragma unroll
            for (int it = 0; it < 4; ++it) {
                const int r = rA + it * 32;
                cp16(sa + (uint32_t)(r * PITCH + c4) * 4u,
                     x + (size_t)(mBase + r) * D_MODEL + kBase + c4);
                cp16(sb + (uint32_t)(r * PITCH + c4) * 4u,
                     W + (size_t)(nBase + r) * D_MODEL + kBase + c4);
            }
        }
        asm volatile("cp.async.commit_group;");
    };

    load_stage(0, 0);
    load_stage(1, 1);

    for (int kt = 0; kt < KTILES; ++kt) {
        asm volatile("cp.async.wait_group 1;");
        __syncthreads();
        load_stage(kt + 2, (kt + 2) % STAGES);

        const float* As = smem + (kt % STAGES) * STAGE_FLOATS;
        const float* Bs = As + BM * PITCH;

#pragma unroll
        for (int ks = 0; ks < BK / 8; ++ks) {
            const int k0 = ks * 8;
            uint32_t a[2][4];
            uint32_t bf[8][2];
#pragma unroll
            for (int mt = 0; mt < 2; ++mt) {
                const int mr = warpM * 32 + mt * 16;
                a[mt][0] = f2tf32(As[(mr + lr) * PITCH + k0 + lc]);
                a[mt][1] = f2tf32(As[(mr + 8 + lr) * PITCH + k0 + lc]);
                a[mt][2] = f2tf32(As[(mr + lr) * PITCH + k0 + 4 + lc]);
                a[mt][3] = f2tf32(As[(mr + 8 + lr) * PITCH + k0 + 4 + lc]);
            }
#pragma unroll
            for (int nt = 0; nt < 8; ++nt) {
                const int nr = warpN * 64 + nt * 8 + lr;
                bf[nt][0] = f2tf32(Bs[nr * PITCH + k0 + lc]);
                bf[nt][1] = f2tf32(Bs[nr * PITCH + k0 + 4 + lc]);
            }
#pragma unroll
            for (int mt = 0; mt < 2; ++mt)
#pragma unroll
                for (int nt = 0; nt < 8; ++nt)
                    mma_tf32(acc[mt][nt], a[mt], bf[nt]);
        }
    }

    // Epilogue: c0,c1 sit on adjacent (even,odd) columns = exactly one rotary pair.
#pragma unroll
    for (int mt = 0; mt < 2; ++mt) {
        const int row0 = mBase + warpM * 32 + mt * 16 + lr;
#pragma unroll
        for (int nt = 0; nt < 8; ++nt) {
            const int col = nBase + warpN * 64 + nt * 8 + lc * 2;
            float c0 = acc[mt][nt][0], c1 = acc[mt][nt][1];
            float c2 = acc[mt][nt][2], c3 = acc[mt][nt][3];
            if (mat < 2) {
                const int j  = col >> 1;
                const int m0 = row0 & (SEQ - 1);
                const int m1 = (row0 + 8) & (SEQ - 1);
                const float cs0 = g_cosT[m0 * HALF_D + j], sn0 = g_sinT[m0 * HALF_D + j];
                const float cs1 = g_cosT[m1 * HALF_D + j], sn1 = g_sinT[m1 * HALF_D + j];
                // q_rot[2i]   =  q[2i]*cos + q[2i+1]*sin
                // q_rot[2i+1] = -q[2i]*sin + q[2i+1]*cos
                const float o0 = c0 * cs0 + c1 * sn0;
                const float o1 = c1 * cs0 - c0 * sn0;
                const float o2 = c2 * cs1 + c3 * sn1;
                const float o3 = c3 * cs1 - c2 * sn1;
                c0 = o0; c1 = o1; c2 = o2; c3 = o3;
            }
            *(float2*)(out + (size_t)row0 * D_MODEL + col)        = make_float2(c0, c1);
            *(float2*)(out + (size_t)(row0 + 8) * D_MODEL + col)  = make_float2(c2, c3);
        }
    }
}

// ---------------- attention: one block per batch ----------------
__global__ __launch_bounds__(256)
void attn_kernel(float* __restrict__ out) {
    __shared__ __align__(16) float qs[16][132];
    __shared__ __align__(16) float ks[16][132];
    __shared__ float at[16][16];

    const int b   = blockIdx.x;
    const int tid = threadIdx.x;
    const float* qb = g_q + (size_t)b * SEQ * D_MODEL;
    const float* kb = g_k + (size_t)b * SEQ * D_MODEL;
    const float* vb = g_v + (size_t)b * SEQ * D_MODEL;

    const int m = tid >> 4, n = tid & 15;
    float s = 0.f;

    for (int ch = 0; ch < D_MODEL / 128; ++ch) {
        __syncthreads();
#pragma unroll
        for (int i = tid; i < 16 * 32; i += 256) {
            const int r = i >> 5, cc = (i & 31) * 4;
            const float4 q4 = *(const float4*)(qb + (size_t)r * D_MODEL + ch * 128 + cc);
            const float4 k4 = *(const float4*)(kb + (size_t)r * D_MODEL + ch * 128 + cc);
            *(float4*)&qs[r][cc] = q4;
            *(float4*)&ks[r][cc] = k4;
        }
        __syncthreads();
#pragma unroll
        for (int d = 0; d < 128; ++d) s += qs[m][d] * ks[n][d];
    }
    s *= rsqrtf((float)D_MODEL);

    // softmax over n (16 lanes per row, rows live in half-warps)
    float mx = s;
#pragma unroll
    for (int off = 8; off; off >>= 1)
        mx = fmaxf(mx, __shfl_xor_sync(0xffffffffu, mx, off, 16));
    const float p = __expf(s - mx);
    float sum = p;
#pragma unroll
    for (int off = 8; off; off >>= 1)
        sum += __shfl_xor_sync(0xffffffffu, sum, off, 16);
    at[m][n] = p / sum;
    __syncthreads();

    // out[m][e] = sum_n at[m][n] * v[n][e]; 4 m-rows per thread-group, 64 e-lanes
    const int mg = tid >> 6;
    const int et = tid & 63;
    float aw[4][16];
#pragma unroll
    for (int mm = 0; mm < 4; ++mm)
#pragma unroll
        for (int nn = 0; nn < 16; ++nn) aw[mm][nn] = at[mg * 4 + mm][nn];

    float* ob = out + (size_t)b * SEQ * D_MODEL;
    for (int e = et; e < D_MODEL; e += 64) {
        float acc[4] = {0.f, 0.f, 0.f, 0.f};
#pragma unroll
        for (int nn = 0; nn < 16; ++nn) {
            const float vv = vb[(size_t)nn * D_MODEL + e];
#pragma unroll
            for (int mm = 0; mm < 4; ++mm) acc[mm] += aw[mm][nn] * vv;
        }
#pragma unroll
        for (int mm = 0; mm < 4; ++mm)
            ob[(size_t)(mg * 4 + mm) * D_MODEL + e] = acc[mm];
    }
}

// ---------------- launch ----------------
extern "C" void kernel_launch(void* const* d_in, const int* in_sizes, int n_in,
                              void* d_out, int out_size) {
    const float* x  = (const float*)d_in[0];
    const float* wq = (const float*)d_in[1];
    const float* wk = (const float*)d_in[2];
    const float* wv = (const float*)d_in[3];
    float* out = (float*)d_out;

    cudaFuncSetAttribute(qkv_gemm_kernel,
                         cudaFuncAttributeMaxDynamicSharedMemorySize, SMEM_BYTES);

    rope_tables_kernel<<<(SEQ * HALF_D + 255) / 256, 256>>>();

    dim3 grid(D_MODEL / BN, TOK / BM, 3);   // (16, 32, 3)
    qkv_gemm_kernel<<<grid, 256, SMEM_BYTES>>>(x, wq, wk, wv);

    attn_kernel<<<BATCH, 256>>>(out);
}

// round 3
// speedup vs baseline: 1.0516x; 1.0516x over previous
#include <cuda_runtime.h>
#include <cstdint>
#include <math.h>

#define D_MODEL 2048
#define SEQ 16
#define BATCH 256
#define TOK (BATCH * SEQ)          // 4096
#define HALF_D (D_MODEL / 2)       // 1024

// ---------------- GEMM config ----------------
#define BM 128
#define BN 256
#define BK 32
#define KTILES (D_MODEL / BK)      // 64
#define STAGES 3
#define STAGE_BYTES 49152          // A 128x32x4 = 16K, B 256x32x4 = 32K
#define OFF_B 16384
#define SMEM_TOTAL (STAGES * STAGE_BYTES)   // 147456

// ---------------- device scratch ----------------
// tf32-converted, K-permuted operands (pairs (k, k+4) interleaved per 8-group)
__device__ uint32_t g_xt[TOK * D_MODEL];
__device__ uint32_t g_wt[3][D_MODEL * D_MODEL];
__device__ float g_q[TOK * D_MODEL];
__device__ float g_k[TOK * D_MODEL];
__device__ float g_v[TOK * D_MODEL];
__device__ float g_cosT[SEQ * HALF_D];
__device__ float g_sinT[SEQ * HALF_D];

// ---------------- helpers ----------------
__device__ __forceinline__ uint32_t smem_u32(const void* p) {
    uint32_t a;
    asm("{ .reg .u64 t; cvta.to.shared.u64 t, %1; cvt.u32.u64 %0, t; }" : "=r"(a) : "l"(p));
    return a;
}
__device__ __forceinline__ uint32_t f2tf32(float f) {
    uint32_t r;
    asm("cvt.rna.tf32.f32 %0, %1;" : "=r"(r) : "f"(f));
    return r;
}
__device__ __forceinline__ void mma_tf32(float* c, uint32_t a0, uint32_t a1,
                                         uint32_t a2, uint32_t a3,
                                         uint32_t b0, uint32_t b1) {
    asm volatile(
        "mma.sync.aligned.m16n8k8.row.col.f32.tf32.tf32.f32 "
        "{%0,%1,%2,%3}, {%4,%5,%6,%7}, {%8,%9}, {%0,%1,%2,%3};"
        : "+f"(c[0]), "+f"(c[1]), "+f"(c[2]), "+f"(c[3])
        : "r"(a0), "r"(a1), "r"(a2), "r"(a3), "r"(b0), "r"(b1));
}
__device__ __forceinline__ void cp16(uint32_t saddr, const void* gaddr) {
    asm volatile("cp.async.cg.shared.global [%0], [%1], 16;" :: "r"(saddr), "l"(gaddr));
}
#define CP_COMMIT() asm volatile("cp.async.commit_group;" ::: "memory")
#define CP_WAIT1()  asm volatile("cp.async.wait_group 1;" ::: "memory")

// ---------------- rotary tables ----------------
__global__ void rope_tables_kernel() {
    int j = blockIdx.x * blockDim.x + threadIdx.x;
    if (j >= HALF_D) return;
    double theta = pow(10000.0, -2.0 * ((double)j - 1.0) / (double)D_MODEL);
#pragma unroll
    for (int m = 0; m < SEQ; ++m) {
        double ang = (double)m * theta;
        g_cosT[m * HALF_D + j] = (float)cos(ang);
        g_sinT[m * HALF_D + j] = (float)sin(ang);
    }
}

// ---------------- convert to tf32 + permute K pairs ----------------
// out[8g+0..7] = tf32(in[8g+0]), tf32(in[8g+4]), tf32(in[8g+1]), tf32(in[8g+5]),
//                tf32(in[8g+2]), tf32(in[8g+6]), tf32(in[8g+3]), tf32(in[8g+7])
__global__ __launch_bounds__(256)
void convert_kernel(const float* __restrict__ in, uint32_t* __restrict__ out, int n8) {
    int i = blockIdx.x * blockDim.x + threadIdx.x;
    if (i >= n8) return;
    float4 a = ((const float4*)in)[2 * i];
    float4 b = ((const float4*)in)[2 * i + 1];
    uint4 o0, o1;
    o0.x = f2tf32(a.x); o0.y = f2tf32(b.x);
    o0.z = f2tf32(a.y); o0.w = f2tf32(b.y);
    o1.x = f2tf32(a.z); o1.y = f2tf32(b.z);
    o1.z = f2tf32(a.w); o1.w = f2tf32(b.w);
    ((uint4*)out)[2 * i]     = o0;
    ((uint4*)out)[2 * i + 1] = o1;
}

// ---------------- QKV GEMM (tf32 mma.sync) + rotary epilogue ----------------
// grid = (2048/BN=8, 4096/BM=32, 3), block = 256 (8 warps, 2M x 4N, 64x64 warp tiles)
__global__ __launch_bounds__(256, 1)
void qkv_gemm_kernel() {
    extern __shared__ char smem[];
    const uint32_t sb = smem_u32(smem);
    const int tid   = threadIdx.x;
    const int lane  = tid & 31;
    const int wid   = tid >> 5;
    const int warpM = wid >> 2;         // 0..1
    const int warpN = wid & 3;          // 0..3
    const int lr    = lane >> 2;        // 0..7
    const int lc    = lane & 3;         // 0..3
    const uint32_t fr = (uint32_t)(lr & 3);
    const int mat   = blockIdx.z;
    const int mBase = blockIdx.y * BM;
    const int nBase = blockIdx.x * BN;

    const uint32_t* A = g_xt;
    const uint32_t* B = g_wt[mat];

    float acc[4][8][4];
#pragma unroll
    for (int mt = 0; mt < 4; ++mt)
#pragma unroll
        for (int nt = 0; nt < 8; ++nt)
#pragma unroll
            for (int i = 0; i < 4; ++i) acc[mt][nt][i] = 0.f;

    // per-thread row byte offsets within the stage
    uint32_t rowA[4];
    uint32_t rowB[8];
#pragma unroll
    for (int mt = 0; mt < 4; ++mt) rowA[mt] = (uint32_t)(warpM * 64 + mt * 16 + lr) * 128u;
#pragma unroll
    for (int nt = 0; nt < 8; ++nt) rowB[nt] = (uint32_t)(warpN * 64 + nt * 8 + lr) * 128u + OFF_B;

    auto load_stage = [&](int kt, int s) {
        if (kt < KTILES) {
            const uint32_t st = sb + (uint32_t)s * STAGE_BYTES;
            const int kBase = kt * BK;
#pragma unroll
            for (int i = 0; i < 4; ++i) {           // A: 1024 chunks
                const int idx = tid + i * 256;
                const int row = idx >> 3, p = idx & 7;
                const uint32_t off = (uint32_t)row * 128u + (((uint32_t)p << 4) ^ (((uint32_t)(row & 3)) << 5));
                cp16(st + off, A + (size_t)(mBase + row) * D_MODEL + kBase + p * 4);
            }
#pragma unroll
            for (int i = 0; i < 8; ++i) {           // B: 2048 chunks
                const int idx = tid + i * 256;
                const int row = idx >> 3, p = idx & 7;
                const uint32_t off = (uint32_t)row * 128u + (((uint32_t)p << 4) ^ (((uint32_t)(row & 3)) << 5));
                cp16(st + OFF_B + off, B + (size_t)(nBase + row) * D_MODEL + kBase + p * 4);
            }
        }
        CP_COMMIT();
    };

    load_stage(0, 0);
    load_stage(1, 1);

    for (int kt = 0; kt < KTILES; ++kt) {
        CP_WAIT1();
        __syncthreads();
        load_stage(kt + 2, (kt + 2) % STAGES);

        const char* sA = smem + (size_t)(kt % STAGES) * STAGE_BYTES;

#pragma unroll
        for (int ks = 0; ks < 4; ++ks) {
            const uint32_t off = (((uint32_t)ks ^ fr) << 5) | ((uint32_t)lc << 3);
            uint2 aF[4][2];
#pragma unroll
            for (int mt = 0; mt < 4; ++mt) {
                aF[mt][0] = *(const uint2*)(sA + rowA[mt] + off);
                aF[mt][1] = *(const uint2*)(sA + rowA[mt] + 8 * 128 + off);
            }
            uint2 bF[8];
#pragma unroll
            for (int nt = 0; nt < 8; ++nt)
                bF[nt] = *(const uint2*)(sA + rowB[nt] + off);
#pragma unroll
            for (int mt = 0; mt < 4; ++mt)
#pragma unroll
                for (int nt = 0; nt < 8; ++nt)
                    mma_tf32(acc[mt][nt],
                             aF[mt][0].x, aF[mt][1].x, aF[mt][0].y, aF[mt][1].y,
                             bF[nt].x, bF[nt].y);
        }
    }

    // ---------------- epilogue: rotary (q/k) + store ----------------
    float* out = (mat == 0) ? g_q : (mat == 1) ? g_k : g_v;
#pragma unroll
    for (int mt = 0; mt < 4; ++mt) {
        const int row0 = mBase + warpM * 64 + mt * 16 + lr;
        const int m0 = row0 & (SEQ - 1);
        const int m1 = (row0 + 8) & (SEQ - 1);
#pragma unroll
        for (int nt = 0; nt < 8; ++nt) {
            const int col = nBase + warpN * 64 + nt * 8 + lc * 2;
            float c0 = acc[mt][nt][0], c1 = acc[mt][nt][1];
            float c2 = acc[mt][nt][2], c3 = acc[mt][nt][3];
            if (mat < 2) {
                const int j = col >> 1;
                const float cs0 = g_cosT[m0 * HALF_D + j], sn0 = g_sinT[m0 * HALF_D + j];
                const float cs1 = g_cosT[m1 * HALF_D + j], sn1 = g_sinT[m1 * HALF_D + j];
                const float o0 = c0 * cs0 + c1 * sn0;
                const float o1 = c1 * cs0 - c0 * sn0;
                const float o2 = c2 * cs1 + c3 * sn1;
                const float o3 = c3 * cs1 - c2 * sn1;
                c0 = o0; c1 = o1; c2 = o2; c3 = o3;
            }
            *(float2*)(out + (size_t)row0 * D_MODEL + col)       = make_float2(c0, c1);
            *(float2*)(out + (size_t)(row0 + 8) * D_MODEL + col) = make_float2(c2, c3);
        }
    }
}

// ---------------- attention: one block per batch ----------------
__global__ __launch_bounds__(256)
void attn_kernel(float* __restrict__ out) {
    __shared__ __align__(16) float qs[16][132];
    __shared__ __align__(16) float ks[16][132];
    __shared__ float at[16][16];

    const int b   = blockIdx.x;
    const int tid = threadIdx.x;
    const float* qb = g_q + (size_t)b * SEQ * D_MODEL;
    const float* kb = g_k + (size_t)b * SEQ * D_MODEL;
    const float* vb = g_v + (size_t)b * SEQ * D_MODEL;

    const int m = tid >> 4, n = tid & 15;
    float s = 0.f;

    for (int ch = 0; ch < D_MODEL / 128; ++ch) {
        __syncthreads();
#pragma unroll
        for (int i = tid; i < 16 * 32; i += 256) {
            const int r = i >> 5, cc = (i & 31) * 4;
            *(float4*)&qs[r][cc] = *(const float4*)(qb + (size_t)r * D_MODEL + ch * 128 + cc);
            *(float4*)&ks[r][cc] = *(const float4*)(kb + (size_t)r * D_MODEL + ch * 128 + cc);
        }
        __syncthreads();
#pragma unroll
        for (int d = 0; d < 128; ++d) s += qs[m][d] * ks[n][d];
    }
    s *= rsqrtf((float)D_MODEL);

    float mx = s;
#pragma unroll
    for (int off = 8; off; off >>= 1)
        mx = fmaxf(mx, __shfl_xor_sync(0xffffffffu, mx, off, 16));
    const float p = __expf(s - mx);
    float sum = p;
#pragma unroll
    for (int off = 8; off; off >>= 1)
        sum += __shfl_xor_sync(0xffffffffu, sum, off, 16);
    at[m][n] = p / sum;
    __syncthreads();

    const int mg = tid >> 6;
    const int et = tid & 63;
    float aw[4][16];
#pragma unroll
    for (int mm = 0; mm < 4; ++mm)
#pragma unroll
        for (int nn = 0; nn < 16; ++nn) aw[mm][nn] = at[mg * 4 + mm][nn];

    float* ob = out + (size_t)b * SEQ * D_MODEL;
    for (int e = et; e < D_MODEL; e += 64) {
        float acc[4] = {0.f, 0.f, 0.f, 0.f};
#pragma unroll
        for (int nn = 0; nn < 16; ++nn) {
            const float vv = vb[(size_t)nn * D_MODEL + e];
#pragma unroll
            for (int mm = 0; mm < 4; ++mm) acc[mm] += aw[mm][nn] * vv;
        }
#pragma unroll
        for (int mm = 0; mm < 4; ++mm)
            ob[(size_t)(mg * 4 + mm) * D_MODEL + e] = acc[mm];
    }
}

// ---------------- launch ----------------
extern "C" void kernel_launch(void* const* d_in, const int* in_sizes, int n_in,
                              void* d_out, int out_size) {
    const float* x  = (const float*)d_in[0];
    const float* wq = (const float*)d_in[1];
    const float* wk = (const float*)d_in[2];
    const float* wv = (const float*)d_in[3];
    float* out = (float*)d_out;

    cudaFuncSetAttribute(qkv_gemm_kernel,
                         cudaFuncAttributeMaxDynamicSharedMemorySize, SMEM_TOTAL);

    rope_tables_kernel<<<4, 256>>>();

    uint32_t* xt; cudaGetSymbolAddress((void**)&xt, g_xt);
    uint32_t* wt; cudaGetSymbolAddress((void**)&wt, g_wt);
    const int nX8 = TOK * D_MODEL / 8;       // 1M
    const int nW8 = D_MODEL * D_MODEL / 8;   // 512K
    convert_kernel<<<(nX8 + 255) / 256, 256>>>(x, xt, nX8);
    convert_kernel<<<(nW8 + 255) / 256, 256>>>(wq, wt, nW8);
    convert_kernel<<<(nW8 + 255) / 256, 256>>>(wk, wt + (size_t)D_MODEL * D_MODEL, nW8);
    convert_kernel<<<(nW8 + 255) / 256, 256>>>(wv, wt + 2 * (size_t)D_MODEL * D_MODEL, nW8);

    dim3 grid(D_MODEL / BN, TOK / BM, 3);    // (8, 32, 3)
    qkv_gemm_kernel<<<grid, 256, SMEM_TOTAL>>>();

    attn_kernel<<<BATCH, 256>>>(out);
}

// round 7
// speedup vs baseline: 1.0933x; 1.0396x over previous
#include <cuda_runtime.h>
#include <cstdint>
#include <math.h>

#define D_MODEL 2048
#define SEQ 16
#define BATCH 256
#define TOK (BATCH * SEQ)          // 4096
#define HALF_D (D_MODEL / 2)       // 1024

// ---------------- GEMM config ----------------
#define BM 128
#define BN 128
#define BK 32
#define KTILES (D_MODEL / BK)      // 64
#define STAGES 3
#define STAGE_BYTES 32768          // A 128x32x4 = 16K, B 128x32x4 = 16K
#define OFF_B 16384
#define SMEM_TOTAL (STAGES * STAGE_BYTES)   // 98304 -> 2 CTAs/SM (196K < 228K)

// ---------------- device scratch ----------------
// tf32-converted, K-permuted operands (pairs (k, k+4) interleaved per 8-group)
__device__ uint32_t g_xt[TOK * D_MODEL];
__device__ uint32_t g_wt[3][D_MODEL * D_MODEL];
__device__ float g_q[TOK * D_MODEL];
__device__ float g_k[TOK * D_MODEL];
__device__ float g_v[TOK * D_MODEL];
__device__ float g_cosT[SEQ * HALF_D];
__device__ float g_sinT[SEQ * HALF_D];

// ---------------- helpers ----------------
__device__ __forceinline__ uint32_t smem_u32(const void* p) {
    uint32_t a;
    asm("{ .reg .u64 t; cvta.to.shared.u64 t, %1; cvt.u32.u64 %0, t; }" : "=r"(a) : "l"(p));
    return a;
}
__device__ __forceinline__ uint32_t f2tf32(float f) {
    uint32_t r;
    asm("cvt.rna.tf32.f32 %0, %1;" : "=r"(r) : "f"(f));
    return r;
}
__device__ __forceinline__ void mma_tf32(float* c, uint32_t a0, uint32_t a1,
                                         uint32_t a2, uint32_t a3,
                                         uint32_t b0, uint32_t b1) {
    asm volatile(
        "mma.sync.aligned.m16n8k8.row.col.f32.tf32.tf32.f32 "
        "{%0,%1,%2,%3}, {%4,%5,%6,%7}, {%8,%9}, {%0,%1,%2,%3};"
        : "+f"(c[0]), "+f"(c[1]), "+f"(c[2]), "+f"(c[3])
        : "r"(a0), "r"(a1), "r"(a2), "r"(a3), "r"(b0), "r"(b1));
}
__device__ __forceinline__ void cp16(uint32_t saddr, const void* gaddr) {
    asm volatile("cp.async.cg.shared.global [%0], [%1], 16;" :: "r"(saddr), "l"(gaddr));
}
#define CP_COMMIT() asm volatile("cp.async.commit_group;" ::: "memory")
#define CP_WAIT1()  asm volatile("cp.async.wait_group 1;" ::: "memory")

// ---------------- rotary tables ----------------
__global__ void rope_tables_kernel() {
    int j = blockIdx.x * blockDim.x + threadIdx.x;
    if (j >= HALF_D) return;
    double theta = pow(10000.0, -2.0 * ((double)j - 1.0) / (double)D_MODEL);
#pragma unroll
    for (int m = 0; m < SEQ; ++m) {
        double ang = (double)m * theta;
        g_cosT[m * HALF_D + j] = (float)cos(ang);
        g_sinT[m * HALF_D + j] = (float)sin(ang);
    }
}

// ---------------- convert to tf32 + permute K pairs ----------------
__global__ __launch_bounds__(256)
void convert_kernel(const float* __restrict__ in, uint32_t* __restrict__ out, int n8) {
    int i = blockIdx.x * blockDim.x + threadIdx.x;
    if (i >= n8) return;
    float4 a = ((const float4*)in)[2 * i];
    float4 b = ((const float4*)in)[2 * i + 1];
    uint4 o0, o1;
    o0.x = f2tf32(a.x); o0.y = f2tf32(b.x);
    o0.z = f2tf32(a.y); o0.w = f2tf32(b.y);
    o1.x = f2tf32(a.z); o1.y = f2tf32(b.z);
    o1.z = f2tf32(a.w); o1.w = f2tf32(b.w);
    ((uint4*)out)[2 * i]     = o0;
    ((uint4*)out)[2 * i + 1] = o1;
}

// ---------------- QKV GEMM (tf32 mma.sync) + rotary epilogue ----------------
// grid = (2048/BN=16, 4096/BM=32, 3), block = 256 (8 warps, 4M x 2N, 32x64 warp tiles)
// 2 CTAs/SM for latency hiding.
__global__ __launch_bounds__(256, 2)
void qkv_gemm_kernel() {
    extern __shared__ char smem[];
    const uint32_t sb = smem_u32(smem);
    const int tid   = threadIdx.x;
    const int lane  = tid & 31;
    const int wid   = tid >> 5;
    const int warpM = wid >> 1;         // 0..3 -> 32-row slabs
    const int warpN = wid & 1;          // 0..1 -> 64-col slabs
    const int lr    = lane >> 2;        // 0..7
    const int lc    = lane & 3;         // 0..3
    const uint32_t fr = (uint32_t)(lr & 3);
    const int mat   = blockIdx.z;
    const int mBase = blockIdx.y * BM;
    const int nBase = blockIdx.x * BN;

    const uint32_t* A = g_xt;
    const uint32_t* B = g_wt[mat];

    float acc[2][8][4];
#pragma unroll
    for (int mt = 0; mt < 2; ++mt)
#pragma unroll
        for (int nt = 0; nt < 8; ++nt)
#pragma unroll
            for (int i = 0; i < 4; ++i) acc[mt][nt][i] = 0.f;

    uint32_t rowA[2];
    uint32_t rowB[8];
#pragma unroll
    for (int mt = 0; mt < 2; ++mt) rowA[mt] = (uint32_t)(warpM * 32 + mt * 16 + lr) * 128u;
#pragma unroll
    for (int nt = 0; nt < 8; ++nt) rowB[nt] = (uint32_t)(warpN * 64 + nt * 8 + lr) * 128u + OFF_B;

    auto load_stage = [&](int kt, int s) {
        if (kt < KTILES) {
            const uint32_t st = sb + (uint32_t)s * STAGE_BYTES;
            const int kBase = kt * BK;
#pragma unroll
            for (int i = 0; i < 4; ++i) {           // A: 1024 16B-chunks
                const int idx = tid + i * 256;
                const int row = idx >> 3, p = idx & 7;
                const uint32_t off = (uint32_t)row * 128u + (((uint32_t)p << 4) ^ (((uint32_t)(row & 3)) << 5));
                cp16(st + off, A + (size_t)(mBase + row) * D_MODEL + kBase + p * 4);
            }
#pragma unroll
            for (int i = 0; i < 4; ++i) {           // B: 1024 16B-chunks
                const int idx = tid + i * 256;
                const int row = idx >> 3, p = idx & 7;
                const uint32_t off = (uint32_t)row * 128u + (((uint32_t)p << 4) ^ (((uint32_t)(row & 3)) << 5));
                cp16(st + OFF_B + off, B + (size_t)(nBase + row) * D_MODEL + kBase + p * 4);
            }
        }
        CP_COMMIT();
    };

    load_stage(0, 0);
    load_stage(1, 1);

    for (int kt = 0; kt < KTILES; ++kt) {
        CP_WAIT1();
        __syncthreads();
        load_stage(kt + 2, (kt + 2) % STAGES);

        const char* sA = smem + (size_t)(kt % STAGES) * STAGE_BYTES;

#pragma unroll
        for (int ks = 0; ks < 4; ++ks) {
            const uint32_t off = (((uint32_t)ks ^ fr) << 5) | ((uint32_t)lc << 3);
            uint2 aF[2][2];
#pragma unroll
            for (int mt = 0; mt < 2; ++mt) {
                aF[mt][0] = *(const uint2*)(sA + rowA[mt] + off);
                aF[mt][1] = *(const uint2*)(sA + rowA[mt] + 8 * 128 + off);
            }
            uint2 bF[8];
#pragma unroll
            for (int nt = 0; nt < 8; ++nt)
                bF[nt] = *(const uint2*)(sA + rowB[nt] + off);
#pragma unroll
            for (int mt = 0; mt < 2; ++mt)
#pragma unroll
                for (int nt = 0; nt < 8; ++nt)
                    mma_tf32(acc[mt][nt],
                             aF[mt][0].x, aF[mt][1].x, aF[mt][0].y, aF[mt][1].y,
                             bF[nt].x, bF[nt].y);
        }
    }

    // ---------------- epilogue: rotary (q/k) + store ----------------
    float* out = (mat == 0) ? g_q : (mat == 1) ? g_k : g_v;
#pragma unroll
    for (int mt = 0; mt < 2; ++mt) {
        const int row0 = mBase + warpM * 32 + mt * 16 + lr;
        const int m0 = row0 & (SEQ - 1);
        const int m1 = (row0 + 8) & (SEQ - 1);
#pragma unroll
        for (int nt = 0; nt < 8; ++nt) {
            const int col = nBase + warpN * 64 + nt * 8 + lc * 2;
            float c0 = acc[mt][nt][0], c1 = acc[mt][nt][1];
            float c2 = acc[mt][nt][2], c3 = acc[mt][nt][3];
            if (mat < 2) {
                const int j = col >> 1;
                const float cs0 = g_cosT[m0 * HALF_D + j], sn0 = g_sinT[m0 * HALF_D + j];
                const float cs1 = g_cosT[m1 * HALF_D + j], sn1 = g_sinT[m1 * HALF_D + j];
                const float o0 = c0 * cs0 + c1 * sn0;
                const float o1 = c1 * cs0 - c0 * sn0;
                const float o2 = c2 * cs1 + c3 * sn1;
                const float o3 = c3 * cs1 - c2 * sn1;
                c0 = o0; c1 = o1; c2 = o2; c3 = o3;
            }
            *(float2*)(out + (size_t)row0 * D_MODEL + col)       = make_float2(c0, c1);
            *(float2*)(out + (size_t)(row0 + 8) * D_MODEL + col) = make_float2(c2, c3);
        }
    }
}

// ---------------- attention: one block per batch ----------------
__global__ __launch_bounds__(256)
void attn_kernel(float* __restrict__ out) {
    __shared__ __align__(16) float qs[16][132];
    __shared__ __align__(16) float ks[16][132];
    __shared__ float at[16][16];

    const int b   = blockIdx.x;
    const int tid = threadIdx.x;
    const float* qb = g_q + (size_t)b * SEQ * D_MODEL;
    const float* kb = g_k + (size_t)b * SEQ * D_MODEL;
    const float* vb = g_v + (size_t)b * SEQ * D_MODEL;

    const int m = tid >> 4, n = tid & 15;
    float s = 0.f;

    for (int ch = 0; ch < D_MODEL / 128; ++ch) {
        __syncthreads();
#pragma unroll
        for (int i = tid; i < 16 * 32; i += 256) {
            const int r = i >> 5, cc = (i & 31) * 4;
            *(float4*)&qs[r][cc] = *(const float4*)(qb + (size_t)r * D_MODEL + ch * 128 + cc);
            *(float4*)&ks[r][cc] = *(const float4*)(kb + (size_t)r * D_MODEL + ch * 128 + cc);
        }
        __syncthreads();
#pragma unroll
        for (int d = 0; d < 128; ++d) s += qs[m][d] * ks[n][d];
    }
    s *= rsqrtf((float)D_MODEL);

    float mx = s;
#pragma unroll
    for (int off = 8; off; off >>= 1)
        mx = fmaxf(mx, __shfl_xor_sync(0xffffffffu, mx, off, 16));
    const float p = __expf(s - mx);
    float sum = p;
#pragma unroll
    for (int off = 8; off; off >>= 1)
        sum += __shfl_xor_sync(0xffffffffu, sum, off, 16);
    at[m][n] = p / sum;
    __syncthreads();

    const int mg = tid >> 6;
    const int et = tid & 63;
    float aw[4][16];
#pragma unroll
    for (int mm = 0; mm < 4; ++mm)
#pragma unroll
        for (int nn = 0; nn < 16; ++nn) aw[mm][nn] = at[mg * 4 + mm][nn];

    float* ob = out + (size_t)b * SEQ * D_MODEL;
    for (int e = et; e < D_MODEL; e += 64) {
        float acc[4] = {0.f, 0.f, 0.f, 0.f};
#pragma unroll
        for (int nn = 0; nn < 16; ++nn) {
            const float vv = vb[(size_t)nn * D_MODEL + e];
#pragma unroll
            for (int mm = 0; mm < 4; ++mm) acc[mm] += aw[mm][nn] * vv;
        }
#pragma unroll
        for (int mm = 0; mm < 4; ++mm)
            ob[(size_t)(mg * 4 + mm) * D_MODEL + e] = acc[mm];
    }
}

// ---------------- launch ----------------
extern "C" void kernel_launch(void* const* d_in, const int* in_sizes, int n_in,
                              void* d_out, int out_size) {
    const float* x  = (const float*)d_in[0];
    const float* wq = (const float*)d_in[1];
    const float* wk = (const float*)d_in[2];
    const float* wv = (const float*)d_in[3];
    float* out = (float*)d_out;

    cudaFuncSetAttribute(qkv_gemm_kernel,
                         cudaFuncAttributeMaxDynamicSharedMemorySize, SMEM_TOTAL);

    rope_tables_kernel<<<4, 256>>>();

    uint32_t* xt; cudaGetSymbolAddress((void**)&xt, g_xt);
    uint32_t* wt; cudaGetSymbolAddress((void**)&wt, g_wt);
    const int nX8 = TOK * D_MODEL / 8;       // 1M
    const int nW8 = D_MODEL * D_MODEL / 8;   // 512K
    convert_kernel<<<(nX8 + 255) / 256, 256>>>(x, xt, nX8);
    convert_kernel<<<(nW8 + 255) / 256, 256>>>(wq, wt, nW8);
    convert_kernel<<<(nW8 + 255) / 256, 256>>>(wk, wt + (size_t)D_MODEL * D_MODEL, nW8);
    convert_kernel<<<(nW8 + 255) / 256, 256>>>(wv, wt + 2 * (size_t)D_MODEL * D_MODEL, nW8);

    dim3 grid(D_MODEL / BN, TOK / BM, 3);    // (16, 32, 3)
    qkv_gemm_kernel<<<grid, 256, SMEM_TOTAL>>>();

    attn_kernel<<<BATCH, 256>>>(out);
}